// round 15
// baseline (speedup 1.0000x reference)
#include <cuda_runtime.h>
#include <cuda_fp16.h>
#include <cstdint>

#define SEQ 2048
#define BATCH 2
#define DMODEL 1024
#define NHEADS 16
#define DHEAD 64
#define BHD (BATCH*NHEADS)

// ---------------------------------------------------------------------------
// Scratch (allocation-free rule: __device__ globals).
// ---------------------------------------------------------------------------
#define QKV_ELEMS (BHD*SEQ*DHEAD)       // 4,194,304
__device__ float g_scratch[4 * QKV_ELEMS];
#define HF_BASE ((__half*)g_scratch)
#define G_QHI (HF_BASE)
#define G_QLO (HF_BASE + 1*QKV_ELEMS)
#define G_KHI (HF_BASE + 2*QKV_ELEMS)
#define G_KLO (HF_BASE + 3*QKV_ELEMS)
#define G_VHI (HF_BASE + 4*QKV_ELEMS)
#define G_VLO (HF_BASE + 5*QKV_ELEMS)
#define G_IHI (HF_BASE + 6*QKV_ELEMS)   // inter hi fp16 [B,S,D]
#define G_ILO (HF_BASE + 7*QKV_ELEMS)   // inter lo

#define RES_ELEMS (BATCH*SEQ*DMODEL)        // 4,194,304
#define WA_ELEMS  (3*DMODEL*DMODEL)         // 3,145,728
#define WO_ELEMS  (DMODEL*DMODEL)           // 1,048,576
__device__ __half g_ops[2*RES_ELEMS + 2*WA_ELEMS + 2*WO_ELEMS];
#define G_RESHI (g_ops)
#define G_RESLO (g_ops + RES_ELEMS)
#define G_WAHI  (g_ops + 2*RES_ELEMS)
#define G_WALO  (g_ops + 2*RES_ELEMS + WA_ELEMS)
#define G_WOHI  (g_ops + 2*RES_ELEMS + 2*WA_ELEMS)
#define G_WOLO  (g_ops + 2*RES_ELEMS + 2*WA_ELEMS + WO_ELEMS)

// ---------------------------------------------------------------------------
// Helpers
// ---------------------------------------------------------------------------
__device__ __forceinline__ uint32_t smem_u32(const void* p) {
    uint32_t a;
    asm("{ .reg .u64 t; cvta.to.shared.u64 t, %1; cvt.u32.u64 %0, t; }"
        : "=r"(a) : "l"(p));
    return a;
}
__device__ __forceinline__ void cp_async16(uint32_t saddr, const void* gptr) {
    asm volatile("cp.async.cg.shared.global [%0], [%1], 16;"
                 :: "r"(saddr), "l"(gptr));
}
#define CP_COMMIT() asm volatile("cp.async.commit_group;" ::: "memory")
#define CP_WAIT0()  asm volatile("cp.async.wait_group 0;" ::: "memory")
#define CP_WAIT1()  asm volatile("cp.async.wait_group 1;" ::: "memory")

// fp16 inputs, fp32 accumulate (full-rate pass for hi*hi)
__device__ __forceinline__ void mma_f32acc(float c[4],
    uint32_t a0, uint32_t a1, uint32_t a2, uint32_t a3,
    uint32_t b0, uint32_t b1)
{
    asm volatile(
        "mma.sync.aligned.m16n8k16.row.col.f32.f16.f16.f32 "
        "{%0,%1,%2,%3}, {%4,%5,%6,%7}, {%8,%9}, {%0,%1,%2,%3};"
        : "+f"(c[0]), "+f"(c[1]), "+f"(c[2]), "+f"(c[3])
        : "r"(a0), "r"(a1), "r"(a2), "r"(a3), "r"(b0), "r"(b1));
}

// fp16 inputs, fp16 accumulate (double-rate pass for the small lo terms)
__device__ __forceinline__ void mma_f16acc(uint32_t& d0, uint32_t& d1,
    uint32_t a0, uint32_t a1, uint32_t a2, uint32_t a3,
    uint32_t b0, uint32_t b1)
{
    asm volatile(
        "mma.sync.aligned.m16n8k16.row.col.f16.f16.f16.f16 "
        "{%0,%1}, {%2,%3,%4,%5}, {%6,%7}, {%0,%1};"
        : "+r"(d0), "+r"(d1)
        : "r"(a0), "r"(a1), "r"(a2), "r"(a3), "r"(b0), "r"(b1));
}

// unpack f16x2 pair accumulator into the fp32 fragment
__device__ __forceinline__ void add_f16acc(float c[4], uint32_t d0, uint32_t d1)
{
    float2 x0 = __half22float2(*(__half2*)&d0);
    float2 x1 = __half22float2(*(__half2*)&d1);
    c[0] += x0.x; c[1] += x0.y; c[2] += x1.x; c[3] += x1.y;
}

__device__ __forceinline__ void pack_hilo(float p0, float p1,
                                          uint32_t& hi, uint32_t& lo)
{
    __half2 h = __floats2half2_rn(p0, p1);
    float r0 = p0 - __half2float(h.x);
    float r1 = p1 - __half2float(h.y);
    __half2 l = __floats2half2_rn(r0, r1);
    hi = *(uint32_t*)&h;
    lo = *(uint32_t*)&l;
}

// ---------------------------------------------------------------------------
// Streaming fp32 -> fp16 hi/lo split (WHICH: 0 res, 1 W_attn, 2 W_O).
// ---------------------------------------------------------------------------
template<int WHICH>
__global__ __launch_bounds__(256)
void cvt_hilo(const float* __restrict__ src, int n4)
{
    __half* hi = (WHICH == 0) ? G_RESHI : (WHICH == 1) ? G_WAHI : G_WOHI;
    __half* lo = (WHICH == 0) ? G_RESLO : (WHICH == 1) ? G_WALO : G_WOLO;
    const int i = blockIdx.x * 256 + threadIdx.x;
    if (i >= n4) return;
    float4 v = ((const float4*)src)[i];
    uint32_t h01, l01, h23, l23;
    pack_hilo(v.x, v.y, h01, l01);
    pack_hilo(v.z, v.w, h23, l23);
    ((uint2*)hi)[i] = make_uint2(h01, h23);
    ((uint2*)lo)[i] = make_uint2(l01, l23);
}

// ---------------------------------------------------------------------------
// fp16 2-pass-equivalent GEMM: C = f32acc(Ahi*Bhi) + f16acc(Ahi*Blo + Alo*Bhi)
// Pre-split operands, cp.async double-buffered tiles, scalar fragment LDS
// (R11 layout; ldmatrix reverted after R13 regression). CTA tile 128x128,
// K-chunk 32. MODE 1: A=res,B=W_attn, q/k/v epilogue. MODE 2: A=inter,B=W_O.
// ---------------------------------------------------------------------------
#define LDA 40
#define TSZ (128 * LDA * 2)                    // one tile: 10240 B
#define TILESET (4 * TSZ)                      // 40960 B
#define GEMM_SMEM_BYTES (2 * TILESET)          // 81920 B

__device__ __forceinline__ void stage_tile16(uint32_t tb,
    const __half* __restrict__ src, int Kd, int tid)
{
#pragma unroll
    for (int i = 0; i < 2; i++) {
        const int l = tid + i * 256;
        const int row = l >> 2;
        const int seg = l & 3;
        cp_async16(tb + (uint32_t)(row * LDA + seg * 8) * 2,
                   src + (size_t)row * Kd + seg * 8);
    }
}

template<int MODE>
__global__ __launch_bounds__(256, 2)
void tc_gemm(const float* __restrict__ bias, float* __restrict__ C,
             int M, int N, int Kd)
{
    extern __shared__ __align__(16) char dyn[];
    const uint32_t sbase = smem_u32(dyn);

    const int tid  = threadIdx.x;
    const int wid  = tid >> 5;
    const int lane = tid & 31;
    const int m0 = blockIdx.y * 128;
    const int n0 = blockIdx.x * 128;
    const int wm = (wid & 3) * 32;
    const int wn = (wid >> 2) * 64;

    const __half* Ahi0 = ((MODE == 1) ? G_RESHI : G_IHI) + (size_t)m0 * Kd;
    const __half* Alo0 = ((MODE == 1) ? G_RESLO : G_ILO) + (size_t)m0 * Kd;
    const __half* Bhi0 = ((MODE == 1) ? G_WAHI  : G_WOHI) + (size_t)n0 * Kd;
    const __half* Blo0 = ((MODE == 1) ? G_WALO  : G_WOLO) + (size_t)n0 * Kd;

    float c[2][8][4];
#pragma unroll
    for (int mf = 0; mf < 2; mf++)
#pragma unroll
        for (int nf = 0; nf < 8; nf++)
#pragma unroll
            for (int e = 0; e < 4; e++) c[mf][nf][e] = 0.f;

    const int nchunk = Kd >> 5;

    {
        const uint32_t bb = sbase;
        stage_tile16(bb,           Ahi0, Kd, tid);
        stage_tile16(bb + TSZ,     Alo0, Kd, tid);
        stage_tile16(bb + 2 * TSZ, Bhi0, Kd, tid);
        stage_tile16(bb + 3 * TSZ, Blo0, Kd, tid);
        CP_COMMIT();
    }

    for (int ch = 0; ch < nchunk; ch++) {
        __syncthreads();                      // prior MMA done (buffer reuse)
        if (ch + 1 < nchunk) {
            const int k1 = (ch + 1) * 32;
            const uint32_t bb = sbase + (uint32_t)((ch + 1) & 1) * TILESET;
            stage_tile16(bb,           Ahi0 + k1, Kd, tid);
            stage_tile16(bb + TSZ,     Alo0 + k1, Kd, tid);
            stage_tile16(bb + 2 * TSZ, Bhi0 + k1, Kd, tid);
            stage_tile16(bb + 3 * TSZ, Blo0 + k1, Kd, tid);
            CP_COMMIT();
            CP_WAIT1();
        } else {
            CP_WAIT0();
        }
        __syncthreads();                      // chunk ch visible

        const uint16_t* Ahi = (const uint16_t*)(dyn + (ch & 1) * TILESET);
        const uint16_t* Alo = Ahi + 128 * LDA;
        const uint16_t* Bhi = Alo + 128 * LDA;
        const uint16_t* Blo = Bhi + 128 * LDA;

#pragma unroll
        for (int ks = 0; ks < 2; ks++) {
            const int kc = ks * 16;
            const int arow = wm + (lane >> 2);
            const int acol = kc + (lane & 3) * 2;

            uint32_t ah[2][4], al[2][4];
#pragma unroll
            for (int mf = 0; mf < 2; mf++) {
                const int r = arow + mf * 16;
                ah[mf][0] = *(const uint32_t*)&Ahi[(r    ) * LDA + acol    ];
                ah[mf][1] = *(const uint32_t*)&Ahi[(r + 8) * LDA + acol    ];
                ah[mf][2] = *(const uint32_t*)&Ahi[(r    ) * LDA + acol + 8];
                ah[mf][3] = *(const uint32_t*)&Ahi[(r + 8) * LDA + acol + 8];
                al[mf][0] = *(const uint32_t*)&Alo[(r    ) * LDA + acol    ];
                al[mf][1] = *(const uint32_t*)&Alo[(r + 8) * LDA + acol    ];
                al[mf][2] = *(const uint32_t*)&Alo[(r    ) * LDA + acol + 8];
                al[mf][3] = *(const uint32_t*)&Alo[(r + 8) * LDA + acol + 8];
            }

#pragma unroll
            for (int nf = 0; nf < 8; nf++) {
                const int nrow = wn + nf * 8 + (lane >> 2);
                const int bcol = kc + (lane & 3) * 2;
                uint32_t bh0 = *(const uint32_t*)&Bhi[nrow * LDA + bcol    ];
                uint32_t bh1 = *(const uint32_t*)&Bhi[nrow * LDA + bcol + 8];
                uint32_t bl0 = *(const uint32_t*)&Blo[nrow * LDA + bcol    ];
                uint32_t bl1 = *(const uint32_t*)&Blo[nrow * LDA + bcol + 8];
#pragma unroll
                for (int mf = 0; mf < 2; mf++) {
                    mma_f32acc(c[mf][nf], ah[mf][0], ah[mf][1], ah[mf][2], ah[mf][3],
                               bh0, bh1);
                    uint32_t d0 = 0u, d1 = 0u;
                    mma_f16acc(d0, d1, ah[mf][0], ah[mf][1], ah[mf][2], ah[mf][3],
                               bl0, bl1);
                    mma_f16acc(d0, d1, al[mf][0], al[mf][1], al[mf][2], al[mf][3],
                               bh0, bh1);
                    add_f16acc(c[mf][nf], d0, d1);
                }
            }
        }
    }

    // ---- epilogue ----
#pragma unroll
    for (int mf = 0; mf < 2; mf++) {
#pragma unroll
        for (int nf = 0; nf < 8; nf++) {
            const int n = n0 + wn + nf * 8 + (lane & 3) * 2;
            const float2 bv = *(const float2*)(bias + n);
#pragma unroll
            for (int half_ = 0; half_ < 2; half_++) {
                const int m = m0 + wm + mf * 16 + (lane >> 2) + half_ * 8;
                float2 r;
                r.x = c[mf][nf][half_ * 2 + 0] + bv.x;
                r.y = c[mf][nf][half_ * 2 + 1] + bv.y;
                if (MODE != 1) {
                    *(float2*)(C + (size_t)m * N + n) = r;
                } else {
                    const int which = n >> 10;
                    const int d = n & 1023;
                    const int h = d >> 6;
                    const int dh = d & 63;
                    const int b_ = m >> 11;
                    const int s_ = m & 2047;
                    const int bh_ = b_ * NHEADS + h;
                    uint32_t hv, lv;
                    pack_hilo(r.x, r.y, hv, lv);
                    if (which < 2) {
                        const size_t idx = ((size_t)bh_ * SEQ + s_) * DHEAD + dh;
                        __half* hid = (which == 0) ? G_QHI : G_KHI;
                        __half* lod = (which == 0) ? G_QLO : G_KLO;
                        *(uint32_t*)(hid + idx) = hv;
                        *(uint32_t*)(lod + idx) = lv;
                    } else {
                        const size_t idx = ((size_t)bh_ * DHEAD + dh) * SEQ + s_;
                        __half2 h2 = *(__half2*)&hv;
                        __half2 l2v = *(__half2*)&lv;
                        G_VHI[idx]       = h2.x;
                        G_VHI[idx + SEQ] = h2.y;
                        G_VLO[idx]       = l2v.x;
                        G_VLO[idx + SEQ] = l2v.y;
                    }
                }
            }
        }
    }
}

// ---------------------------------------------------------------------------
// Tensor-core causal flash attention, fp16 2-pass-equivalent scheme.
// Scalar fragment LDS (R11 layout). Epilogue writes inter fp16 hi/lo.
// ---------------------------------------------------------------------------
#define AST 72
#define ATTN_SMEM_BYTES ((2*128*AST + 4*64*AST) * 2)   // 73728 B

__global__ __launch_bounds__(256, 2)
void attn_mma()
{
    extern __shared__ __align__(16) uint16_t smb[];
    uint16_t* Qh = smb;                   // [128][72]
    uint16_t* Ql = Qh + 128 * AST;
    uint16_t* Kh = Ql + 128 * AST;        // [64][72]  (key, dh)
    uint16_t* Kl = Kh + 64 * AST;
    uint16_t* Vh = Kl + 64 * AST;         // [64][72]  (dh, key)
    uint16_t* Vl = Vh + 64 * AST;

    const int bh = blockIdx.x;
    const int qt = (int)(gridDim.y - 1 - blockIdx.y);
    const int q0 = qt * 128;
    const int tid  = threadIdx.x;
    const int wq   = tid >> 5;
    const int lane = tid & 31;
    const int g  = lane >> 2;
    const int t4 = lane & 3;

    const uint16_t* qhi = (const uint16_t*)G_QHI;
    const uint16_t* qlo = (const uint16_t*)G_QLO;
    const uint16_t* khi = (const uint16_t*)G_KHI;
    const uint16_t* klo = (const uint16_t*)G_KLO;
    const uint16_t* vhi = (const uint16_t*)G_VHI;
    const uint16_t* vlo = (const uint16_t*)G_VLO;

    {
        const int r  = tid >> 1;
        const int c0 = (tid & 1) * 32;
        const size_t gi = ((size_t)bh * SEQ + q0 + r) * DHEAD + c0;
        const uint4* s1 = (const uint4*)(qhi + gi);
        const uint4* s2 = (const uint4*)(qlo + gi);
        uint4* d1 = (uint4*)(Qh + r * AST + c0);
        uint4* d2 = (uint4*)(Ql + r * AST + c0);
#pragma unroll
        for (int i = 0; i < 4; i++) { d1[i] = s1[i]; d2[i] = s2[i]; }
    }

    float o[8][4];
#pragma unroll
    for (int nf = 0; nf < 8; nf++)
#pragma unroll
        for (int e = 0; e < 4; e++) o[nf][e] = 0.f;
    float m2[2] = {-1e30f, -1e30f};
    float l2[2] = {0.f, 0.f};

    const int r0 = wq * 16;
    const int nkt = 2 * qt + 2;

    for (int kt = 0; kt < nkt; kt++) {
        const int k0 = kt * 64;
        __syncthreads();
        {
            const int r  = tid >> 2;
            const int c0 = (tid & 3) * 16;
            const size_t ki = ((size_t)bh * SEQ + k0 + r) * DHEAD + c0;
            *(uint4*)(Kh + r * AST + c0)     = *(const uint4*)(khi + ki);
            *(uint4*)(Kh + r * AST + c0 + 8) = *(const uint4*)(khi + ki + 8);
            *(uint4*)(Kl + r * AST + c0)     = *(const uint4*)(klo + ki);
            *(uint4*)(Kl + r * AST + c0 + 8) = *(const uint4*)(klo + ki + 8);
            const size_t vi = ((size_t)bh * DHEAD + r) * SEQ + k0 + c0;
            *(uint4*)(Vh + r * AST + c0)     = *(const uint4*)(vhi + vi);
            *(uint4*)(Vh + r * AST + c0 + 8) = *(const uint4*)(vhi + vi + 8);
            *(uint4*)(Vl + r * AST + c0)     = *(const uint4*)(vlo + vi);
            *(uint4*)(Vl + r * AST + c0 + 8) = *(const uint4*)(vlo + vi + 8);
        }
        __syncthreads();

        // ---- S = Q K^T (hi*hi f32acc + lo-terms f16acc) ----
        float s[8][4];
#pragma unroll
        for (int nf = 0; nf < 8; nf++)
#pragma unroll
            for (int e = 0; e < 4; e++) s[nf][e] = 0.f;

#pragma unroll
        for (int kc = 0; kc < 64; kc += 16) {
            const int ac = kc + 2 * t4;
            uint32_t ah0 = *(const uint32_t*)&Qh[(r0 + g    ) * AST + ac    ];
            uint32_t ah1 = *(const uint32_t*)&Qh[(r0 + g + 8) * AST + ac    ];
            uint32_t ah2 = *(const uint32_t*)&Qh[(r0 + g    ) * AST + ac + 8];
            uint32_t ah3 = *(const uint32_t*)&Qh[(r0 + g + 8) * AST + ac + 8];
            uint32_t al0 = *(const uint32_t*)&Ql[(r0 + g    ) * AST + ac    ];
            uint32_t al1 = *(const uint32_t*)&Ql[(r0 + g + 8) * AST + ac    ];
            uint32_t al2 = *(const uint32_t*)&Ql[(r0 + g    ) * AST + ac + 8];
            uint32_t al3 = *(const uint32_t*)&Ql[(r0 + g + 8) * AST + ac + 8];
#pragma unroll
            for (int nf = 0; nf < 8; nf++) {
                const int kn = nf * 8 + g;
                uint32_t bh0 = *(const uint32_t*)&Kh[kn * AST + ac    ];
                uint32_t bh1 = *(const uint32_t*)&Kh[kn * AST + ac + 8];
                uint32_t bl0 = *(const uint32_t*)&Kl[kn * AST + ac    ];
                uint32_t bl1 = *(const uint32_t*)&Kl[kn * AST + ac + 8];
                mma_f32acc(s[nf], ah0, ah1, ah2, ah3, bh0, bh1);
                uint32_t d0 = 0u, d1 = 0u;
                mma_f16acc(d0, d1, ah0, ah1, ah2, ah3, bl0, bl1);
                mma_f16acc(d0, d1, al0, al1, al2, al3, bh0, bh1);
                add_f16acc(s[nf], d0, d1);
            }
        }

#pragma unroll
        for (int nf = 0; nf < 8; nf++)
#pragma unroll
            for (int e = 0; e < 4; e++) s[nf][e] *= 0.125f;

        if (kt >= 2 * qt) {
#pragma unroll
            for (int nf = 0; nf < 8; nf++)
#pragma unroll
                for (int e = 0; e < 4; e++) {
                    const int col = k0 + nf * 8 + t4 * 2 + (e & 1);
                    const int row = q0 + r0 + g + ((e >> 1) ? 8 : 0);
                    if (col > row) s[nf][e] = -1e30f;
                }
        }

#pragma unroll
        for (int h = 0; h < 2; h++) {
            float mx = -1e30f;
#pragma unroll
            for (int nf = 0; nf < 8; nf++)
                mx = fmaxf(mx, fmaxf(s[nf][2 * h], s[nf][2 * h + 1]));
            mx = fmaxf(mx, __shfl_xor_sync(0xffffffffu, mx, 1));
            mx = fmaxf(mx, __shfl_xor_sync(0xffffffffu, mx, 2));
            const float mnew = fmaxf(m2[h], mx);
            const float corr = __expf(m2[h] - mnew);
            float ps = 0.f;
#pragma unroll
            for (int nf = 0; nf < 8; nf++) {
                float p0 = __expf(s[nf][2 * h    ] - mnew);
                float p1 = __expf(s[nf][2 * h + 1] - mnew);
                s[nf][2 * h] = p0; s[nf][2 * h + 1] = p1;
                ps += p0 + p1;
            }
            ps += __shfl_xor_sync(0xffffffffu, ps, 1);
            ps += __shfl_xor_sync(0xffffffffu, ps, 2);
            l2[h] = l2[h] * corr + ps;
            m2[h] = mnew;
#pragma unroll
            for (int nf = 0; nf < 8; nf++) {
                o[nf][2 * h] *= corr; o[nf][2 * h + 1] *= corr;
            }
        }

        // ---- O += P V (hi*hi f32acc + lo-terms f16acc), P from registers ----
#pragma unroll
        for (int kg = 0; kg < 4; kg++) {
            uint32_t pa0, pa1, pa2, pa3, pl0, pl1, pl2, pl3;
            pack_hilo(s[2 * kg    ][0], s[2 * kg    ][1], pa0, pl0);
            pack_hilo(s[2 * kg    ][2], s[2 * kg    ][3], pa1, pl1);
            pack_hilo(s[2 * kg + 1][0], s[2 * kg + 1][1], pa2, pl2);
            pack_hilo(s[2 * kg + 1][2], s[2 * kg + 1][3], pa3, pl3);
            const int kc = kg * 16 + 2 * t4;
#pragma unroll
            for (int nf = 0; nf < 8; nf++) {
                const int dn = nf * 8 + g;
                uint32_t vh0 = *(const uint32_t*)&Vh[dn * AST + kc    ];
                uint32_t vh1 = *(const uint32_t*)&Vh[dn * AST + kc + 8];
                uint32_t vl0 = *(const uint32_t*)&Vl[dn * AST + kc    ];
                uint32_t vl1 = *(const uint32_t*)&Vl[dn * AST + kc + 8];
                mma_f32acc(o[nf], pa0, pa1, pa2, pa3, vh0, vh1);
                uint32_t d0 = 0u, d1 = 0u;
                mma_f16acc(d0, d1, pa0, pa1, pa2, pa3, vl0, vl1);
                mma_f16acc(d0, d1, pl0, pl1, pl2, pl3, vh0, vh1);
                add_f16acc(o[nf], d0, d1);
            }
        }
    }

    // ---- epilogue: normalize, write inter as fp16 hi/lo [B,S,D] ----
    const int b_ = bh >> 4;
    const int head = bh & 15;
#pragma unroll
    for (int h = 0; h < 2; h++) {
        const float inv = 1.0f / l2[h];
        const int row = q0 + r0 + g + h * 8;
        const size_t base = ((size_t)b_ * SEQ + row) * DMODEL + head * DHEAD;
#pragma unroll
        for (int nf = 0; nf < 8; nf++) {
            uint32_t hv, lv;
            pack_hilo(o[nf][2 * h] * inv, o[nf][2 * h + 1] * inv, hv, lv);
            *(uint32_t*)(G_IHI + base + nf * 8 + 2 * t4) = hv;
            *(uint32_t*)(G_ILO + base + nf * 8 + 2 * t4) = lv;
        }
    }
}

// ---------------------------------------------------------------------------
extern "C" void kernel_launch(void* const* d_in, const int* in_sizes, int n_in,
                              void* d_out, int out_size)
{
    const float* res    = (const float*)d_in[0];  // [2,2048,1024]
    const float* W_attn = (const float*)d_in[1];  // [3072,1024]
    const float* b_attn = (const float*)d_in[2];  // [3072]
    const float* W_O    = (const float*)d_in[3];  // [1024,1024]
    const float* b_O    = (const float*)d_in[4];  // [1024]
    float* out = (float*)d_out;                   // [2,2048,1024]

    cudaFuncSetAttribute(tc_gemm<1>, cudaFuncAttributeMaxDynamicSharedMemorySize,
                         GEMM_SMEM_BYTES);
    cudaFuncSetAttribute(tc_gemm<2>, cudaFuncAttributeMaxDynamicSharedMemorySize,
                         GEMM_SMEM_BYTES);
    cudaFuncSetAttribute(attn_mma, cudaFuncAttributeMaxDynamicSharedMemorySize,
                         ATTN_SMEM_BYTES);

    // 0. Pre-split inputs to fp16 hi/lo
    cvt_hilo<0><<<RES_ELEMS / 4 / 256, 256>>>(res,    RES_ELEMS / 4);
    cvt_hilo<1><<<WA_ELEMS  / 4 / 256, 256>>>(W_attn, WA_ELEMS / 4);
    cvt_hilo<2><<<WO_ELEMS  / 4 / 256, 256>>>(W_O,    WO_ELEMS / 4);

    // 1. QKV projection + fp16 q/k/v epilogue
    {
        dim3 grid(3 * DMODEL / 128, BATCH * SEQ / 128);   // (24, 32)
        tc_gemm<1><<<grid, 256, GEMM_SMEM_BYTES>>>(b_attn, nullptr,
                                                   BATCH * SEQ, 3 * DMODEL, DMODEL);
    }
    // 2. Causal attention
    {
        dim3 grid(BHD, SEQ / 128);                         // (32, 16)
        attn_mma<<<grid, 256, ATTN_SMEM_BYTES>>>();
    }
    // 3. Output projection (A = inter hi/lo)
    {
        dim3 grid(DMODEL / 128, BATCH * SEQ / 128);        // (8, 32)
        tc_gemm<2><<<grid, 256, GEMM_SMEM_BYTES>>>(b_O, out,
                                                   BATCH * SEQ, DMODEL, DMODEL);
    }
}

// round 16
// speedup vs baseline: 1.3974x; 1.3974x over previous
#include <cuda_runtime.h>
#include <cuda_fp16.h>
#include <cstdint>

#define SEQ 2048
#define BATCH 2
#define DMODEL 1024
#define NHEADS 16
#define DHEAD 64
#define BHD (BATCH*NHEADS)

// ---------------------------------------------------------------------------
// Scratch (allocation-free rule: __device__ globals).
// g_scratch (64MB): q/k/v hi+lo fp16 (v transposed), inter hi+lo fp16.
// g_ops (24MB): res hi/lo fp16, W_attn single fp16, W_O single fp16.
// ---------------------------------------------------------------------------
#define QKV_ELEMS (BHD*SEQ*DHEAD)       // 4,194,304
__device__ float g_scratch[4 * QKV_ELEMS];
#define HF_BASE ((__half*)g_scratch)
#define G_QHI (HF_BASE)
#define G_QLO (HF_BASE + 1*QKV_ELEMS)
#define G_KHI (HF_BASE + 2*QKV_ELEMS)
#define G_KLO (HF_BASE + 3*QKV_ELEMS)
#define G_VHI (HF_BASE + 4*QKV_ELEMS)
#define G_VLO (HF_BASE + 5*QKV_ELEMS)
#define G_IHI (HF_BASE + 6*QKV_ELEMS)   // inter hi fp16 [B,S,D]
#define G_ILO (HF_BASE + 7*QKV_ELEMS)   // inter lo

#define RES_ELEMS (BATCH*SEQ*DMODEL)        // 4,194,304
#define WA_ELEMS  (3*DMODEL*DMODEL)         // 3,145,728
#define WO_ELEMS  (DMODEL*DMODEL)           // 1,048,576
__device__ __half g_ops[2*RES_ELEMS + WA_ELEMS + WO_ELEMS];
#define G_RESHI (g_ops)
#define G_RESLO (g_ops + RES_ELEMS)
#define G_WA    (g_ops + 2*RES_ELEMS)
#define G_WO    (g_ops + 2*RES_ELEMS + WA_ELEMS)

// ---------------------------------------------------------------------------
// Helpers
// ---------------------------------------------------------------------------
__device__ __forceinline__ uint32_t smem_u32(const void* p) {
    uint32_t a;
    asm("{ .reg .u64 t; cvta.to.shared.u64 t, %1; cvt.u32.u64 %0, t; }"
        : "=r"(a) : "l"(p));
    return a;
}
__device__ __forceinline__ void cp_async16(uint32_t saddr, const void* gptr) {
    asm volatile("cp.async.cg.shared.global [%0], [%1], 16;"
                 :: "r"(saddr), "l"(gptr));
}
#define CP_COMMIT() asm volatile("cp.async.commit_group;" ::: "memory")
#define CP_WAIT0()  asm volatile("cp.async.wait_group 0;" ::: "memory")
#define CP_WAIT1()  asm volatile("cp.async.wait_group 1;" ::: "memory")

// fp16 inputs, fp32 accumulate (the only MMA flavor used — f16acc regressed in R15)
__device__ __forceinline__ void mma_f32acc(float c[4],
    uint32_t a0, uint32_t a1, uint32_t a2, uint32_t a3,
    uint32_t b0, uint32_t b1)
{
    asm volatile(
        "mma.sync.aligned.m16n8k16.row.col.f32.f16.f16.f32 "
        "{%0,%1,%2,%3}, {%4,%5,%6,%7}, {%8,%9}, {%0,%1,%2,%3};"
        : "+f"(c[0]), "+f"(c[1]), "+f"(c[2]), "+f"(c[3])
        : "r"(a0), "r"(a1), "r"(a2), "r"(a3), "r"(b0), "r"(b1));
}

__device__ __forceinline__ void pack_hilo(float p0, float p1,
                                          uint32_t& hi, uint32_t& lo)
{
    __half2 h = __floats2half2_rn(p0, p1);
    float r0 = p0 - __half2float(h.x);
    float r1 = p1 - __half2float(h.y);
    __half2 l = __floats2half2_rn(r0, r1);
    hi = *(uint32_t*)&h;
    lo = *(uint32_t*)&l;
}

// ---------------------------------------------------------------------------
// Streaming converters.
// cvt_hilo: fp32 -> fp16 hi/lo (res). cvt_single<W>: fp32 -> fp16 (weights).
// ---------------------------------------------------------------------------
__global__ __launch_bounds__(256)
void cvt_res(const float* __restrict__ src, int n4)
{
    const int i = blockIdx.x * 256 + threadIdx.x;
    if (i >= n4) return;
    float4 v = ((const float4*)src)[i];
    uint32_t h01, l01, h23, l23;
    pack_hilo(v.x, v.y, h01, l01);
    pack_hilo(v.z, v.w, h23, l23);
    ((uint2*)G_RESHI)[i] = make_uint2(h01, h23);
    ((uint2*)G_RESLO)[i] = make_uint2(l01, l23);
}

template<int WHICH>   // 0: W_attn, 1: W_O
__global__ __launch_bounds__(256)
void cvt_w(const float* __restrict__ src, int n4)
{
    __half* dst = (WHICH == 0) ? G_WA : G_WO;
    const int i = blockIdx.x * 256 + threadIdx.x;
    if (i >= n4) return;
    float4 v = ((const float4*)src)[i];
    __half2 h01 = __floats2half2_rn(v.x, v.y);
    __half2 h23 = __floats2half2_rn(v.z, v.w);
    ((uint2*)dst)[i] = make_uint2(*(uint32_t*)&h01, *(uint32_t*)&h23);
}

// ---------------------------------------------------------------------------
// 2-pass asymmetric GEMM: C = (Ahi + Alo) * B_f16^T + bias.
// A split exactly (fp16 hi/lo); B single-rounded fp16 (error ~2^-12 rel).
// cp.async double-buffered, 3 tiles/buffer, scalar fragment LDS (R11 layout).
// MODE 1: A=res, B=W_attn, q/k/v hi/lo epilogue. MODE 2: A=inter, B=W_O.
// ---------------------------------------------------------------------------
#define LDA 40
#define TSZ (128 * LDA * 2)                    // one tile: 10240 B
#define TILESET3 (3 * TSZ)                     // 30720 B
#define GEMM_SMEM_BYTES (2 * TILESET3)         // 61440 B

__device__ __forceinline__ void stage_tile16(uint32_t tb,
    const __half* __restrict__ src, int Kd, int tid)
{
#pragma unroll
    for (int i = 0; i < 2; i++) {
        const int l = tid + i * 256;
        const int row = l >> 2;
        const int seg = l & 3;
        cp_async16(tb + (uint32_t)(row * LDA + seg * 8) * 2,
                   src + (size_t)row * Kd + seg * 8);
    }
}

template<int MODE>
__global__ __launch_bounds__(256, 2)
void tc_gemm(const float* __restrict__ bias, float* __restrict__ C,
             int M, int N, int Kd)
{
    extern __shared__ __align__(16) char dyn[];
    const uint32_t sbase = smem_u32(dyn);

    const int tid  = threadIdx.x;
    const int wid  = tid >> 5;
    const int lane = tid & 31;
    const int m0 = blockIdx.y * 128;
    const int n0 = blockIdx.x * 128;
    const int wm = (wid & 3) * 32;
    const int wn = (wid >> 2) * 64;

    const __half* Ahi0 = ((MODE == 1) ? G_RESHI : G_IHI) + (size_t)m0 * Kd;
    const __half* Alo0 = ((MODE == 1) ? G_RESLO : G_ILO) + (size_t)m0 * Kd;
    const __half* B0   = ((MODE == 1) ? G_WA    : G_WO ) + (size_t)n0 * Kd;

    float c[2][8][4];
#pragma unroll
    for (int mf = 0; mf < 2; mf++)
#pragma unroll
        for (int nf = 0; nf < 8; nf++)
#pragma unroll
            for (int e = 0; e < 4; e++) c[mf][nf][e] = 0.f;

    const int nchunk = Kd >> 5;

    {
        const uint32_t bb = sbase;
        stage_tile16(bb,           Ahi0, Kd, tid);
        stage_tile16(bb + TSZ,     Alo0, Kd, tid);
        stage_tile16(bb + 2 * TSZ, B0,   Kd, tid);
        CP_COMMIT();
    }

    for (int ch = 0; ch < nchunk; ch++) {
        __syncthreads();                      // prior MMA done (buffer reuse)
        if (ch + 1 < nchunk) {
            const int k1 = (ch + 1) * 32;
            const uint32_t bb = sbase + (uint32_t)((ch + 1) & 1) * TILESET3;
            stage_tile16(bb,           Ahi0 + k1, Kd, tid);
            stage_tile16(bb + TSZ,     Alo0 + k1, Kd, tid);
            stage_tile16(bb + 2 * TSZ, B0   + k1, Kd, tid);
            CP_COMMIT();
            CP_WAIT1();
        } else {
            CP_WAIT0();
        }
        __syncthreads();                      // chunk ch visible

        const uint16_t* Ahi = (const uint16_t*)(dyn + (ch & 1) * TILESET3);
        const uint16_t* Alo = Ahi + 128 * LDA;
        const uint16_t* Bs  = Alo + 128 * LDA;

#pragma unroll
        for (int ks = 0; ks < 2; ks++) {
            const int kc = ks * 16;
            const int arow = wm + (lane >> 2);
            const int acol = kc + (lane & 3) * 2;

            uint32_t ah[2][4], al[2][4];
#pragma unroll
            for (int mf = 0; mf < 2; mf++) {
                const int r = arow + mf * 16;
                ah[mf][0] = *(const uint32_t*)&Ahi[(r    ) * LDA + acol    ];
                ah[mf][1] = *(const uint32_t*)&Ahi[(r + 8) * LDA + acol    ];
                ah[mf][2] = *(const uint32_t*)&Ahi[(r    ) * LDA + acol + 8];
                ah[mf][3] = *(const uint32_t*)&Ahi[(r + 8) * LDA + acol + 8];
                al[mf][0] = *(const uint32_t*)&Alo[(r    ) * LDA + acol    ];
                al[mf][1] = *(const uint32_t*)&Alo[(r + 8) * LDA + acol    ];
                al[mf][2] = *(const uint32_t*)&Alo[(r    ) * LDA + acol + 8];
                al[mf][3] = *(const uint32_t*)&Alo[(r + 8) * LDA + acol + 8];
            }

#pragma unroll
            for (int nf = 0; nf < 8; nf++) {
                const int nrow = wn + nf * 8 + (lane >> 2);
                const int bcol = kc + (lane & 3) * 2;
                uint32_t b0 = *(const uint32_t*)&Bs[nrow * LDA + bcol    ];
                uint32_t b1 = *(const uint32_t*)&Bs[nrow * LDA + bcol + 8];
#pragma unroll
                for (int mf = 0; mf < 2; mf++) {
                    mma_f32acc(c[mf][nf], ah[mf][0], ah[mf][1], ah[mf][2], ah[mf][3],
                               b0, b1);
                    mma_f32acc(c[mf][nf], al[mf][0], al[mf][1], al[mf][2], al[mf][3],
                               b0, b1);
                }
            }
        }
    }

    // ---- epilogue ----
#pragma unroll
    for (int mf = 0; mf < 2; mf++) {
#pragma unroll
        for (int nf = 0; nf < 8; nf++) {
            const int n = n0 + wn + nf * 8 + (lane & 3) * 2;
            const float2 bv = *(const float2*)(bias + n);
#pragma unroll
            for (int half_ = 0; half_ < 2; half_++) {
                const int m = m0 + wm + mf * 16 + (lane >> 2) + half_ * 8;
                float2 r;
                r.x = c[mf][nf][half_ * 2 + 0] + bv.x;
                r.y = c[mf][nf][half_ * 2 + 1] + bv.y;
                if (MODE != 1) {
                    *(float2*)(C + (size_t)m * N + n) = r;
                } else {
                    const int which = n >> 10;
                    const int d = n & 1023;
                    const int h = d >> 6;
                    const int dh = d & 63;
                    const int b_ = m >> 11;
                    const int s_ = m & 2047;
                    const int bh_ = b_ * NHEADS + h;
                    uint32_t hv, lv;
                    pack_hilo(r.x, r.y, hv, lv);
                    if (which < 2) {
                        const size_t idx = ((size_t)bh_ * SEQ + s_) * DHEAD + dh;
                        __half* hid = (which == 0) ? G_QHI : G_KHI;
                        __half* lod = (which == 0) ? G_QLO : G_KLO;
                        *(uint32_t*)(hid + idx) = hv;
                        *(uint32_t*)(lod + idx) = lv;
                    } else {
                        const size_t idx = ((size_t)bh_ * DHEAD + dh) * SEQ + s_;
                        __half2 h2 = *(__half2*)&hv;
                        __half2 l2v = *(__half2*)&lv;
                        G_VHI[idx]       = h2.x;
                        G_VHI[idx + SEQ] = h2.y;
                        G_VLO[idx]       = l2v.x;
                        G_VLO[idx + SEQ] = l2v.y;
                    }
                }
            }
        }
    }
}

// ---------------------------------------------------------------------------
// Tensor-core causal flash attention: fp16 hi/lo, 3-pass f32acc everywhere
// (R11's proven pattern; precision preserved so attention adds ~no error).
// Epilogue writes inter fp16 hi/lo for the 2-pass proj GEMM.
// ---------------------------------------------------------------------------
#define AST 72
#define ATTN_SMEM_BYTES ((2*128*AST + 4*64*AST) * 2)   // 73728 B

__global__ __launch_bounds__(256, 2)
void attn_mma()
{
    extern __shared__ __align__(16) uint16_t smb[];
    uint16_t* Qh = smb;                   // [128][72]
    uint16_t* Ql = Qh + 128 * AST;
    uint16_t* Kh = Ql + 128 * AST;        // [64][72]  (key, dh)
    uint16_t* Kl = Kh + 64 * AST;
    uint16_t* Vh = Kl + 64 * AST;         // [64][72]  (dh, key)
    uint16_t* Vl = Vh + 64 * AST;

    const int bh = blockIdx.x;
    const int qt = (int)(gridDim.y - 1 - blockIdx.y);
    const int q0 = qt * 128;
    const int tid  = threadIdx.x;
    const int wq   = tid >> 5;
    const int lane = tid & 31;
    const int g  = lane >> 2;
    const int t4 = lane & 3;

    const uint16_t* qhi = (const uint16_t*)G_QHI;
    const uint16_t* qlo = (const uint16_t*)G_QLO;
    const uint16_t* khi = (const uint16_t*)G_KHI;
    const uint16_t* klo = (const uint16_t*)G_KLO;
    const uint16_t* vhi = (const uint16_t*)G_VHI;
    const uint16_t* vlo = (const uint16_t*)G_VLO;

    {
        const int r  = tid >> 1;
        const int c0 = (tid & 1) * 32;
        const size_t gi = ((size_t)bh * SEQ + q0 + r) * DHEAD + c0;
        const uint4* s1 = (const uint4*)(qhi + gi);
        const uint4* s2 = (const uint4*)(qlo + gi);
        uint4* d1 = (uint4*)(Qh + r * AST + c0);
        uint4* d2 = (uint4*)(Ql + r * AST + c0);
#pragma unroll
        for (int i = 0; i < 4; i++) { d1[i] = s1[i]; d2[i] = s2[i]; }
    }

    float o[8][4];
#pragma unroll
    for (int nf = 0; nf < 8; nf++)
#pragma unroll
        for (int e = 0; e < 4; e++) o[nf][e] = 0.f;
    float m2[2] = {-1e30f, -1e30f};
    float l2[2] = {0.f, 0.f};

    const int r0 = wq * 16;
    const int nkt = 2 * qt + 2;

    for (int kt = 0; kt < nkt; kt++) {
        const int k0 = kt * 64;
        __syncthreads();
        {
            const int r  = tid >> 2;
            const int c0 = (tid & 3) * 16;
            const size_t ki = ((size_t)bh * SEQ + k0 + r) * DHEAD + c0;
            *(uint4*)(Kh + r * AST + c0)     = *(const uint4*)(khi + ki);
            *(uint4*)(Kh + r * AST + c0 + 8) = *(const uint4*)(khi + ki + 8);
            *(uint4*)(Kl + r * AST + c0)     = *(const uint4*)(klo + ki);
            *(uint4*)(Kl + r * AST + c0 + 8) = *(const uint4*)(klo + ki + 8);
            const size_t vi = ((size_t)bh * DHEAD + r) * SEQ + k0 + c0;
            *(uint4*)(Vh + r * AST + c0)     = *(const uint4*)(vhi + vi);
            *(uint4*)(Vh + r * AST + c0 + 8) = *(const uint4*)(vhi + vi + 8);
            *(uint4*)(Vl + r * AST + c0)     = *(const uint4*)(vlo + vi);
            *(uint4*)(Vl + r * AST + c0 + 8) = *(const uint4*)(vlo + vi + 8);
        }
        __syncthreads();

        // ---- S = Q K^T (3 passes, all f32acc) ----
        float s[8][4];
#pragma unroll
        for (int nf = 0; nf < 8; nf++)
#pragma unroll
            for (int e = 0; e < 4; e++) s[nf][e] = 0.f;

#pragma unroll
        for (int kc = 0; kc < 64; kc += 16) {
            const int ac = kc + 2 * t4;
            uint32_t ah0 = *(const uint32_t*)&Qh[(r0 + g    ) * AST + ac    ];
            uint32_t ah1 = *(const uint32_t*)&Qh[(r0 + g + 8) * AST + ac    ];
            uint32_t ah2 = *(const uint32_t*)&Qh[(r0 + g    ) * AST + ac + 8];
            uint32_t ah3 = *(const uint32_t*)&Qh[(r0 + g + 8) * AST + ac + 8];
            uint32_t al0 = *(const uint32_t*)&Ql[(r0 + g    ) * AST + ac    ];
            uint32_t al1 = *(const uint32_t*)&Ql[(r0 + g + 8) * AST + ac    ];
            uint32_t al2 = *(const uint32_t*)&Ql[(r0 + g    ) * AST + ac + 8];
            uint32_t al3 = *(const uint32_t*)&Ql[(r0 + g + 8) * AST + ac + 8];
#pragma unroll
            for (int nf = 0; nf < 8; nf++) {
                const int kn = nf * 8 + g;
                uint32_t bh0 = *(const uint32_t*)&Kh[kn * AST + ac    ];
                uint32_t bh1 = *(const uint32_t*)&Kh[kn * AST + ac + 8];
                uint32_t bl0 = *(const uint32_t*)&Kl[kn * AST + ac    ];
                uint32_t bl1 = *(const uint32_t*)&Kl[kn * AST + ac + 8];
                mma_f32acc(s[nf], ah0, ah1, ah2, ah3, bh0, bh1);
                mma_f32acc(s[nf], ah0, ah1, ah2, ah3, bl0, bl1);
                mma_f32acc(s[nf], al0, al1, al2, al3, bh0, bh1);
            }
        }

#pragma unroll
        for (int nf = 0; nf < 8; nf++)
#pragma unroll
            for (int e = 0; e < 4; e++) s[nf][e] *= 0.125f;

        if (kt >= 2 * qt) {
#pragma unroll
            for (int nf = 0; nf < 8; nf++)
#pragma unroll
                for (int e = 0; e < 4; e++) {
                    const int col = k0 + nf * 8 + t4 * 2 + (e & 1);
                    const int row = q0 + r0 + g + ((e >> 1) ? 8 : 0);
                    if (col > row) s[nf][e] = -1e30f;
                }
        }

#pragma unroll
        for (int h = 0; h < 2; h++) {
            float mx = -1e30f;
#pragma unroll
            for (int nf = 0; nf < 8; nf++)
                mx = fmaxf(mx, fmaxf(s[nf][2 * h], s[nf][2 * h + 1]));
            mx = fmaxf(mx, __shfl_xor_sync(0xffffffffu, mx, 1));
            mx = fmaxf(mx, __shfl_xor_sync(0xffffffffu, mx, 2));
            const float mnew = fmaxf(m2[h], mx);
            const float corr = __expf(m2[h] - mnew);
            float ps = 0.f;
#pragma unroll
            for (int nf = 0; nf < 8; nf++) {
                float p0 = __expf(s[nf][2 * h    ] - mnew);
                float p1 = __expf(s[nf][2 * h + 1] - mnew);
                s[nf][2 * h] = p0; s[nf][2 * h + 1] = p1;
                ps += p0 + p1;
            }
            ps += __shfl_xor_sync(0xffffffffu, ps, 1);
            ps += __shfl_xor_sync(0xffffffffu, ps, 2);
            l2[h] = l2[h] * corr + ps;
            m2[h] = mnew;
#pragma unroll
            for (int nf = 0; nf < 8; nf++) {
                o[nf][2 * h] *= corr; o[nf][2 * h + 1] *= corr;
            }
        }

        // ---- O += P V (3 passes, all f32acc), P from registers ----
#pragma unroll
        for (int kg = 0; kg < 4; kg++) {
            uint32_t pa0, pa1, pa2, pa3, pl0, pl1, pl2, pl3;
            pack_hilo(s[2 * kg    ][0], s[2 * kg    ][1], pa0, pl0);
            pack_hilo(s[2 * kg    ][2], s[2 * kg    ][3], pa1, pl1);
            pack_hilo(s[2 * kg + 1][0], s[2 * kg + 1][1], pa2, pl2);
            pack_hilo(s[2 * kg + 1][2], s[2 * kg + 1][3], pa3, pl3);
            const int kc = kg * 16 + 2 * t4;
#pragma unroll
            for (int nf = 0; nf < 8; nf++) {
                const int dn = nf * 8 + g;
                uint32_t vh0 = *(const uint32_t*)&Vh[dn * AST + kc    ];
                uint32_t vh1 = *(const uint32_t*)&Vh[dn * AST + kc + 8];
                uint32_t vl0 = *(const uint32_t*)&Vl[dn * AST + kc    ];
                uint32_t vl1 = *(const uint32_t*)&Vl[dn * AST + kc + 8];
                mma_f32acc(o[nf], pa0, pa1, pa2, pa3, vh0, vh1);
                mma_f32acc(o[nf], pa0, pa1, pa2, pa3, vl0, vl1);
                mma_f32acc(o[nf], pl0, pl1, pl2, pl3, vh0, vh1);
            }
        }
    }

    // ---- epilogue: normalize, write inter as fp16 hi/lo [B,S,D] ----
    const int b_ = bh >> 4;
    const int head = bh & 15;
#pragma unroll
    for (int h = 0; h < 2; h++) {
        const float inv = 1.0f / l2[h];
        const int row = q0 + r0 + g + h * 8;
        const size_t base = ((size_t)b_ * SEQ + row) * DMODEL + head * DHEAD;
#pragma unroll
        for (int nf = 0; nf < 8; nf++) {
            uint32_t hv, lv;
            pack_hilo(o[nf][2 * h] * inv, o[nf][2 * h + 1] * inv, hv, lv);
            *(uint32_t*)(G_IHI + base + nf * 8 + 2 * t4) = hv;
            *(uint32_t*)(G_ILO + base + nf * 8 + 2 * t4) = lv;
        }
    }
}

// ---------------------------------------------------------------------------
extern "C" void kernel_launch(void* const* d_in, const int* in_sizes, int n_in,
                              void* d_out, int out_size)
{
    const float* res    = (const float*)d_in[0];  // [2,2048,1024]
    const float* W_attn = (const float*)d_in[1];  // [3072,1024]
    const float* b_attn = (const float*)d_in[2];  // [3072]
    const float* W_O    = (const float*)d_in[3];  // [1024,1024]
    const float* b_O    = (const float*)d_in[4];  // [1024]
    float* out = (float*)d_out;                   // [2,2048,1024]

    cudaFuncSetAttribute(tc_gemm<1>, cudaFuncAttributeMaxDynamicSharedMemorySize,
                         GEMM_SMEM_BYTES);
    cudaFuncSetAttribute(tc_gemm<2>, cudaFuncAttributeMaxDynamicSharedMemorySize,
                         GEMM_SMEM_BYTES);
    cudaFuncSetAttribute(attn_mma, cudaFuncAttributeMaxDynamicSharedMemorySize,
                         ATTN_SMEM_BYTES);

    // 0. Pre-convert: res -> fp16 hi/lo; weights -> single fp16
    cvt_res<<<RES_ELEMS / 4 / 256, 256>>>(res, RES_ELEMS / 4);
    cvt_w<0><<<WA_ELEMS / 4 / 256, 256>>>(W_attn, WA_ELEMS / 4);
    cvt_w<1><<<WO_ELEMS / 4 / 256, 256>>>(W_O, WO_ELEMS / 4);

    // 1. QKV projection (2-pass asymmetric) + fp16 hi/lo q/k/v epilogue
    {
        dim3 grid(3 * DMODEL / 128, BATCH * SEQ / 128);   // (24, 32)
        tc_gemm<1><<<grid, 256, GEMM_SMEM_BYTES>>>(b_attn, nullptr,
                                                   BATCH * SEQ, 3 * DMODEL, DMODEL);
    }
    // 2. Causal attention (3-pass, precision-preserving)
    {
        dim3 grid(BHD, SEQ / 128);                         // (32, 16)
        attn_mma<<<grid, 256, ATTN_SMEM_BYTES>>>();
    }
    // 3. Output projection (2-pass asymmetric, A = inter hi/lo)
    {
        dim3 grid(DMODEL / 128, BATCH * SEQ / 128);        // (8, 32)
        tc_gemm<2><<<grid, 256, GEMM_SMEM_BYTES>>>(b_O, out,
                                                   BATCH * SEQ, DMODEL, DMODEL);
    }
}

// round 17
// speedup vs baseline: 1.7584x; 1.2583x over previous
#include <cuda_runtime.h>
#include <cuda_fp16.h>
#include <cstdint>

#define SEQ 2048
#define BATCH 2
#define DMODEL 1024
#define NHEADS 16
#define DHEAD 64
#define BHD (BATCH*NHEADS)

// ---------------------------------------------------------------------------
// Scratch (allocation-free rule: __device__ globals).
// g_scratch: q,k [BH,SEQ,Dh] fp16 single; v [BH,Dh,SEQ] fp16 single;
//            inter hi+lo fp16 [B,S,D] (2-pass proj needs the split).
// g_ops: res hi/lo fp16, W_attn single fp16, W_O single fp16.
// ---------------------------------------------------------------------------
#define QKV_ELEMS (BHD*SEQ*DHEAD)       // 4,194,304
__device__ float g_scratch[4 * QKV_ELEMS];
#define HF_BASE ((__half*)g_scratch)
#define G_Q   (HF_BASE)
#define G_K   (HF_BASE + 1*QKV_ELEMS)
#define G_V   (HF_BASE + 2*QKV_ELEMS)
#define G_IHI (HF_BASE + 3*QKV_ELEMS)   // inter hi fp16 [B,S,D]
#define G_ILO (HF_BASE + 4*QKV_ELEMS)   // inter lo

#define RES_ELEMS (BATCH*SEQ*DMODEL)        // 4,194,304
#define WA_ELEMS  (3*DMODEL*DMODEL)         // 3,145,728
#define WO_ELEMS  (DMODEL*DMODEL)           // 1,048,576
__device__ __half g_ops[2*RES_ELEMS + WA_ELEMS + WO_ELEMS];
#define G_RESHI (g_ops)
#define G_RESLO (g_ops + RES_ELEMS)
#define G_WA    (g_ops + 2*RES_ELEMS)
#define G_WO    (g_ops + 2*RES_ELEMS + WA_ELEMS)

// ---------------------------------------------------------------------------
// Helpers
// ---------------------------------------------------------------------------
__device__ __forceinline__ uint32_t smem_u32(const void* p) {
    uint32_t a;
    asm("{ .reg .u64 t; cvta.to.shared.u64 t, %1; cvt.u32.u64 %0, t; }"
        : "=r"(a) : "l"(p));
    return a;
}
__device__ __forceinline__ void cp_async16(uint32_t saddr, const void* gptr) {
    asm volatile("cp.async.cg.shared.global [%0], [%1], 16;"
                 :: "r"(saddr), "l"(gptr));
}
#define CP_COMMIT() asm volatile("cp.async.commit_group;" ::: "memory")
#define CP_WAIT0()  asm volatile("cp.async.wait_group 0;" ::: "memory")
#define CP_WAIT1()  asm volatile("cp.async.wait_group 1;" ::: "memory")

// fp16 inputs, fp32 accumulate (the only MMA flavor used)
__device__ __forceinline__ void mma_f32acc(float c[4],
    uint32_t a0, uint32_t a1, uint32_t a2, uint32_t a3,
    uint32_t b0, uint32_t b1)
{
    asm volatile(
        "mma.sync.aligned.m16n8k16.row.col.f32.f16.f16.f32 "
        "{%0,%1,%2,%3}, {%4,%5,%6,%7}, {%8,%9}, {%0,%1,%2,%3};"
        : "+f"(c[0]), "+f"(c[1]), "+f"(c[2]), "+f"(c[3])
        : "r"(a0), "r"(a1), "r"(a2), "r"(a3), "r"(b0), "r"(b1));
}

__device__ __forceinline__ void pack_hilo(float p0, float p1,
                                          uint32_t& hi, uint32_t& lo)
{
    __half2 h = __floats2half2_rn(p0, p1);
    float r0 = p0 - __half2float(h.x);
    float r1 = p1 - __half2float(h.y);
    __half2 l = __floats2half2_rn(r0, r1);
    hi = *(uint32_t*)&h;
    lo = *(uint32_t*)&l;
}

__device__ __forceinline__ uint32_t pack_single(float p0, float p1)
{
    __half2 h = __floats2half2_rn(p0, p1);
    return *(uint32_t*)&h;
}

// ---------------------------------------------------------------------------
// Streaming converters: res -> fp16 hi/lo; weights -> single fp16.
// ---------------------------------------------------------------------------
__global__ __launch_bounds__(256)
void cvt_res(const float* __restrict__ src, int n4)
{
    const int i = blockIdx.x * 256 + threadIdx.x;
    if (i >= n4) return;
    float4 v = ((const float4*)src)[i];
    uint32_t h01, l01, h23, l23;
    pack_hilo(v.x, v.y, h01, l01);
    pack_hilo(v.z, v.w, h23, l23);
    ((uint2*)G_RESHI)[i] = make_uint2(h01, h23);
    ((uint2*)G_RESLO)[i] = make_uint2(l01, l23);
}

template<int WHICH>   // 0: W_attn, 1: W_O
__global__ __launch_bounds__(256)
void cvt_w(const float* __restrict__ src, int n4)
{
    __half* dst = (WHICH == 0) ? G_WA : G_WO;
    const int i = blockIdx.x * 256 + threadIdx.x;
    if (i >= n4) return;
    float4 v = ((const float4*)src)[i];
    ((uint2*)dst)[i] = make_uint2(pack_single(v.x, v.y), pack_single(v.z, v.w));
}

// ---------------------------------------------------------------------------
// 2-pass asymmetric GEMM: C = (Ahi + Alo) * B_f16^T + bias (R16, unchanged
// core). MODE 1: A=res, B=W_attn, SINGLE-fp16 q/k/v epilogue. MODE 2:
// A=inter hi/lo, B=W_O, fp32 write.
// ---------------------------------------------------------------------------
#define LDA 40
#define TSZ (128 * LDA * 2)                    // one tile: 10240 B
#define TILESET3 (3 * TSZ)                     // 30720 B
#define GEMM_SMEM_BYTES (2 * TILESET3)         // 61440 B

__device__ __forceinline__ void stage_tile16(uint32_t tb,
    const __half* __restrict__ src, int Kd, int tid)
{
#pragma unroll
    for (int i = 0; i < 2; i++) {
        const int l = tid + i * 256;
        const int row = l >> 2;
        const int seg = l & 3;
        cp_async16(tb + (uint32_t)(row * LDA + seg * 8) * 2,
                   src + (size_t)row * Kd + seg * 8);
    }
}

template<int MODE>
__global__ __launch_bounds__(256, 2)
void tc_gemm(const float* __restrict__ bias, float* __restrict__ C,
             int M, int N, int Kd)
{
    extern __shared__ __align__(16) char dyn[];
    const uint32_t sbase = smem_u32(dyn);

    const int tid  = threadIdx.x;
    const int wid  = tid >> 5;
    const int lane = tid & 31;
    const int m0 = blockIdx.y * 128;
    const int n0 = blockIdx.x * 128;
    const int wm = (wid & 3) * 32;
    const int wn = (wid >> 2) * 64;

    const __half* Ahi0 = ((MODE == 1) ? G_RESHI : G_IHI) + (size_t)m0 * Kd;
    const __half* Alo0 = ((MODE == 1) ? G_RESLO : G_ILO) + (size_t)m0 * Kd;
    const __half* B0   = ((MODE == 1) ? G_WA    : G_WO ) + (size_t)n0 * Kd;

    float c[2][8][4];
#pragma unroll
    for (int mf = 0; mf < 2; mf++)
#pragma unroll
        for (int nf = 0; nf < 8; nf++)
#pragma unroll
            for (int e = 0; e < 4; e++) c[mf][nf][e] = 0.f;

    const int nchunk = Kd >> 5;

    {
        const uint32_t bb = sbase;
        stage_tile16(bb,           Ahi0, Kd, tid);
        stage_tile16(bb + TSZ,     Alo0, Kd, tid);
        stage_tile16(bb + 2 * TSZ, B0,   Kd, tid);
        CP_COMMIT();
    }

    for (int ch = 0; ch < nchunk; ch++) {
        __syncthreads();                      // prior MMA done (buffer reuse)
        if (ch + 1 < nchunk) {
            const int k1 = (ch + 1) * 32;
            const uint32_t bb = sbase + (uint32_t)((ch + 1) & 1) * TILESET3;
            stage_tile16(bb,           Ahi0 + k1, Kd, tid);
            stage_tile16(bb + TSZ,     Alo0 + k1, Kd, tid);
            stage_tile16(bb + 2 * TSZ, B0   + k1, Kd, tid);
            CP_COMMIT();
            CP_WAIT1();
        } else {
            CP_WAIT0();
        }
        __syncthreads();                      // chunk ch visible

        const uint16_t* Ahi = (const uint16_t*)(dyn + (ch & 1) * TILESET3);
        const uint16_t* Alo = Ahi + 128 * LDA;
        const uint16_t* Bs  = Alo + 128 * LDA;

#pragma unroll
        for (int ks = 0; ks < 2; ks++) {
            const int kc = ks * 16;
            const int arow = wm + (lane >> 2);
            const int acol = kc + (lane & 3) * 2;

            uint32_t ah[2][4], al[2][4];
#pragma unroll
            for (int mf = 0; mf < 2; mf++) {
                const int r = arow + mf * 16;
                ah[mf][0] = *(const uint32_t*)&Ahi[(r    ) * LDA + acol    ];
                ah[mf][1] = *(const uint32_t*)&Ahi[(r + 8) * LDA + acol    ];
                ah[mf][2] = *(const uint32_t*)&Ahi[(r    ) * LDA + acol + 8];
                ah[mf][3] = *(const uint32_t*)&Ahi[(r + 8) * LDA + acol + 8];
                al[mf][0] = *(const uint32_t*)&Alo[(r    ) * LDA + acol    ];
                al[mf][1] = *(const uint32_t*)&Alo[(r + 8) * LDA + acol    ];
                al[mf][2] = *(const uint32_t*)&Alo[(r    ) * LDA + acol + 8];
                al[mf][3] = *(const uint32_t*)&Alo[(r + 8) * LDA + acol + 8];
            }

#pragma unroll
            for (int nf = 0; nf < 8; nf++) {
                const int nrow = wn + nf * 8 + (lane >> 2);
                const int bcol = kc + (lane & 3) * 2;
                uint32_t b0 = *(const uint32_t*)&Bs[nrow * LDA + bcol    ];
                uint32_t b1 = *(const uint32_t*)&Bs[nrow * LDA + bcol + 8];
#pragma unroll
                for (int mf = 0; mf < 2; mf++) {
                    mma_f32acc(c[mf][nf], ah[mf][0], ah[mf][1], ah[mf][2], ah[mf][3],
                               b0, b1);
                    mma_f32acc(c[mf][nf], al[mf][0], al[mf][1], al[mf][2], al[mf][3],
                               b0, b1);
                }
            }
        }
    }

    // ---- epilogue ----
#pragma unroll
    for (int mf = 0; mf < 2; mf++) {
#pragma unroll
        for (int nf = 0; nf < 8; nf++) {
            const int n = n0 + wn + nf * 8 + (lane & 3) * 2;
            const float2 bv = *(const float2*)(bias + n);
#pragma unroll
            for (int half_ = 0; half_ < 2; half_++) {
                const int m = m0 + wm + mf * 16 + (lane >> 2) + half_ * 8;
                float2 r;
                r.x = c[mf][nf][half_ * 2 + 0] + bv.x;
                r.y = c[mf][nf][half_ * 2 + 1] + bv.y;
                if (MODE != 1) {
                    *(float2*)(C + (size_t)m * N + n) = r;
                } else {
                    const int which = n >> 10;
                    const int d = n & 1023;
                    const int h = d >> 6;
                    const int dh = d & 63;
                    const int b_ = m >> 11;
                    const int s_ = m & 2047;
                    const int bh_ = b_ * NHEADS + h;
                    if (which < 2) {
                        const size_t idx = ((size_t)bh_ * SEQ + s_) * DHEAD + dh;
                        __half* dst = (which == 0) ? G_Q : G_K;
                        *(uint32_t*)(dst + idx) = pack_single(r.x, r.y);
                    } else {
                        // v transposed single: [bh][dh][s]
                        const size_t idx = ((size_t)bh_ * DHEAD + dh) * SEQ + s_;
                        G_V[idx]       = __float2half_rn(r.x);
                        G_V[idx + SEQ] = __float2half_rn(r.y);
                    }
                }
            }
        }
    }
}

// ---------------------------------------------------------------------------
// Standard single-fp16 FA2 causal attention (1 MMA pass per GEMM).
// Q/K/V single fp16; errors ~1.4e-4 (S) + 2.4e-4 (P) + 2.4e-4 (V) per the
// calibrated model. Epilogue writes inter fp16 hi/lo for the 2-pass proj.
// ---------------------------------------------------------------------------
#define AST 72
#define ATTN_SMEM_BYTES ((128*AST + 64*AST + 64*AST) * 2)   // 36864 B

__global__ __launch_bounds__(256, 2)
void attn_mma()
{
    extern __shared__ __align__(16) uint16_t smb[];
    uint16_t* Qs = smb;                   // [128][72]
    uint16_t* Ks = Qs + 128 * AST;        // [64][72]  (key, dh)
    uint16_t* Vs = Ks + 64 * AST;         // [64][72]  (dh, key)

    const int bh = blockIdx.x;
    const int qt = (int)(gridDim.y - 1 - blockIdx.y);
    const int q0 = qt * 128;
    const int tid  = threadIdx.x;
    const int wq   = tid >> 5;
    const int lane = tid & 31;
    const int g  = lane >> 2;
    const int t4 = lane & 3;

    const uint16_t* qg = (const uint16_t*)G_Q;
    const uint16_t* kg = (const uint16_t*)G_K;
    const uint16_t* vg = (const uint16_t*)G_V;

    // stage Q (single): 128 x 64 halves
    {
        const int r  = tid >> 1;
        const int c0 = (tid & 1) * 32;
        const size_t gi = ((size_t)bh * SEQ + q0 + r) * DHEAD + c0;
        const uint4* s1 = (const uint4*)(qg + gi);
        uint4* d1 = (uint4*)(Qs + r * AST + c0);
#pragma unroll
        for (int i = 0; i < 4; i++) d1[i] = s1[i];
    }

    float o[8][4];
#pragma unroll
    for (int nf = 0; nf < 8; nf++)
#pragma unroll
        for (int e = 0; e < 4; e++) o[nf][e] = 0.f;
    float m2[2] = {-1e30f, -1e30f};
    float l2[2] = {0.f, 0.f};

    const int r0 = wq * 16;
    const int nkt = 2 * qt + 2;

    for (int kt = 0; kt < nkt; kt++) {
        const int k0 = kt * 64;
        __syncthreads();
        {
            const int r  = tid >> 2;           // 0..63
            const int c0 = (tid & 3) * 16;     // 0,16,32,48
            const size_t ki = ((size_t)bh * SEQ + k0 + r) * DHEAD + c0;
            *(uint4*)(Ks + r * AST + c0)     = *(const uint4*)(kg + ki);
            *(uint4*)(Ks + r * AST + c0 + 8) = *(const uint4*)(kg + ki + 8);
            const size_t vi = ((size_t)bh * DHEAD + r) * SEQ + k0 + c0;
            *(uint4*)(Vs + r * AST + c0)     = *(const uint4*)(vg + vi);
            *(uint4*)(Vs + r * AST + c0 + 8) = *(const uint4*)(vg + vi + 8);
        }
        __syncthreads();

        // ---- S = Q K^T (single pass) ----
        float s[8][4];
#pragma unroll
        for (int nf = 0; nf < 8; nf++)
#pragma unroll
            for (int e = 0; e < 4; e++) s[nf][e] = 0.f;

#pragma unroll
        for (int kc = 0; kc < 64; kc += 16) {
            const int ac = kc + 2 * t4;
            uint32_t a0 = *(const uint32_t*)&Qs[(r0 + g    ) * AST + ac    ];
            uint32_t a1 = *(const uint32_t*)&Qs[(r0 + g + 8) * AST + ac    ];
            uint32_t a2 = *(const uint32_t*)&Qs[(r0 + g    ) * AST + ac + 8];
            uint32_t a3 = *(const uint32_t*)&Qs[(r0 + g + 8) * AST + ac + 8];
#pragma unroll
            for (int nf = 0; nf < 8; nf++) {
                const int kn = nf * 8 + g;
                uint32_t b0 = *(const uint32_t*)&Ks[kn * AST + ac    ];
                uint32_t b1 = *(const uint32_t*)&Ks[kn * AST + ac + 8];
                mma_f32acc(s[nf], a0, a1, a2, a3, b0, b1);
            }
        }

#pragma unroll
        for (int nf = 0; nf < 8; nf++)
#pragma unroll
            for (int e = 0; e < 4; e++) s[nf][e] *= 0.125f;

        if (kt >= 2 * qt) {
#pragma unroll
            for (int nf = 0; nf < 8; nf++)
#pragma unroll
                for (int e = 0; e < 4; e++) {
                    const int col = k0 + nf * 8 + t4 * 2 + (e & 1);
                    const int row = q0 + r0 + g + ((e >> 1) ? 8 : 0);
                    if (col > row) s[nf][e] = -1e30f;
                }
        }

#pragma unroll
        for (int h = 0; h < 2; h++) {
            float mx = -1e30f;
#pragma unroll
            for (int nf = 0; nf < 8; nf++)
                mx = fmaxf(mx, fmaxf(s[nf][2 * h], s[nf][2 * h + 1]));
            mx = fmaxf(mx, __shfl_xor_sync(0xffffffffu, mx, 1));
            mx = fmaxf(mx, __shfl_xor_sync(0xffffffffu, mx, 2));
            const float mnew = fmaxf(m2[h], mx);
            const float corr = __expf(m2[h] - mnew);
            float ps = 0.f;
#pragma unroll
            for (int nf = 0; nf < 8; nf++) {
                float p0 = __expf(s[nf][2 * h    ] - mnew);
                float p1 = __expf(s[nf][2 * h + 1] - mnew);
                s[nf][2 * h] = p0; s[nf][2 * h + 1] = p1;
                ps += p0 + p1;
            }
            ps += __shfl_xor_sync(0xffffffffu, ps, 1);
            ps += __shfl_xor_sync(0xffffffffu, ps, 2);
            l2[h] = l2[h] * corr + ps;
            m2[h] = mnew;
#pragma unroll
            for (int nf = 0; nf < 8; nf++) {
                o[nf][2 * h] *= corr; o[nf][2 * h + 1] *= corr;
            }
        }

        // ---- O += P V (single pass), P single fp16 from registers ----
#pragma unroll
        for (int kg2 = 0; kg2 < 4; kg2++) {
            uint32_t pa0 = pack_single(s[2 * kg2    ][0], s[2 * kg2    ][1]);
            uint32_t pa1 = pack_single(s[2 * kg2    ][2], s[2 * kg2    ][3]);
            uint32_t pa2 = pack_single(s[2 * kg2 + 1][0], s[2 * kg2 + 1][1]);
            uint32_t pa3 = pack_single(s[2 * kg2 + 1][2], s[2 * kg2 + 1][3]);
            const int kc = kg2 * 16 + 2 * t4;
#pragma unroll
            for (int nf = 0; nf < 8; nf++) {
                const int dn = nf * 8 + g;
                uint32_t v0 = *(const uint32_t*)&Vs[dn * AST + kc    ];
                uint32_t v1 = *(const uint32_t*)&Vs[dn * AST + kc + 8];
                mma_f32acc(o[nf], pa0, pa1, pa2, pa3, v0, v1);
            }
        }
    }

    // ---- epilogue: normalize, write inter as fp16 hi/lo [B,S,D] ----
    const int b_ = bh >> 4;
    const int head = bh & 15;
#pragma unroll
    for (int h = 0; h < 2; h++) {
        const float inv = 1.0f / l2[h];
        const int row = q0 + r0 + g + h * 8;
        const size_t base = ((size_t)b_ * SEQ + row) * DMODEL + head * DHEAD;
#pragma unroll
        for (int nf = 0; nf < 8; nf++) {
            uint32_t hv, lv;
            pack_hilo(o[nf][2 * h] * inv, o[nf][2 * h + 1] * inv, hv, lv);
            *(uint32_t*)(G_IHI + base + nf * 8 + 2 * t4) = hv;
            *(uint32_t*)(G_ILO + base + nf * 8 + 2 * t4) = lv;
        }
    }
}

// ---------------------------------------------------------------------------
extern "C" void kernel_launch(void* const* d_in, const int* in_sizes, int n_in,
                              void* d_out, int out_size)
{
    const float* res    = (const float*)d_in[0];  // [2,2048,1024]
    const float* W_attn = (const float*)d_in[1];  // [3072,1024]
    const float* b_attn = (const float*)d_in[2];  // [3072]
    const float* W_O    = (const float*)d_in[3];  // [1024,1024]
    const float* b_O    = (const float*)d_in[4];  // [1024]
    float* out = (float*)d_out;                   // [2,2048,1024]

    cudaFuncSetAttribute(tc_gemm<1>, cudaFuncAttributeMaxDynamicSharedMemorySize,
                         GEMM_SMEM_BYTES);
    cudaFuncSetAttribute(tc_gemm<2>, cudaFuncAttributeMaxDynamicSharedMemorySize,
                         GEMM_SMEM_BYTES);
    cudaFuncSetAttribute(attn_mma, cudaFuncAttributeMaxDynamicSharedMemorySize,
                         ATTN_SMEM_BYTES);

    // 0. Pre-convert: res -> fp16 hi/lo; weights -> single fp16
    cvt_res<<<RES_ELEMS / 4 / 256, 256>>>(res, RES_ELEMS / 4);
    cvt_w<0><<<WA_ELEMS / 4 / 256, 256>>>(W_attn, WA_ELEMS / 4);
    cvt_w<1><<<WO_ELEMS / 4 / 256, 256>>>(W_O, WO_ELEMS / 4);

    // 1. QKV projection (2-pass asymmetric) + single-fp16 q/k/v epilogue
    {
        dim3 grid(3 * DMODEL / 128, BATCH * SEQ / 128);   // (24, 32)
        tc_gemm<1><<<grid, 256, GEMM_SMEM_BYTES>>>(b_attn, nullptr,
                                                   BATCH * SEQ, 3 * DMODEL, DMODEL);
    }
    // 2. Causal attention (single-fp16 FA2, 1-pass MMAs)
    {
        dim3 grid(BHD, SEQ / 128);                         // (32, 16)
        attn_mma<<<grid, 256, ATTN_SMEM_BYTES>>>();
    }
    // 3. Output projection (2-pass asymmetric, A = inter hi/lo)
    {
        dim3 grid(DMODEL / 128, BATCH * SEQ / 128);        // (8, 32)
        tc_gemm<2><<<grid, 256, GEMM_SMEM_BYTES>>>(b_O, out,
                                                   BATCH * SEQ, DMODEL, DMODEL);
    }
}